// round 13
// baseline (speedup 1.0000x reference)
#include <cuda_runtime.h>
#include <cuda_fp16.h>
#include <math.h>

#define NN 50000
#define NBLK 196          // ceil(NN/256)
#define EPS_BN 1e-5f
#define SLOPE 0.01f

typedef unsigned long long u64;

// ---------------- scratch (static device memory; no allocs) ----------------
__device__ int   g_degi[NN];
__device__ int   g_counter;
__device__ int   g_start[NN];
__device__ int   g_end[NN];
__device__ int   g_cur[NN];
__device__ int   g_csr[800000];
__device__ float g_dinv[NN];
// fp16 message buffers: 64 ch = 8 uint4 per node (8 ch per uint4 as 4x half2)
__device__ uint4 g_u1[NN * 8];
__device__ uint4 g_u2[NN * 8];
__device__ uint4 g_u3[NN * 8];
// h1 in fp16: 128 ch = 16 uint4 per node
__device__ uint4 g_h1h[NN * 16];
__device__ float g_acc2[NN * 64];
// stats layout:
// [0:128) sum1  [128:256) sumsq1  [256:384) scale1  [384:512) shift1
// [512:576) sum2 [576:640) sumsq2
__device__ float g_stats[1024];

__device__ __forceinline__ float lrelu(float v) { return v > 0.f ? v : SLOPE * v; }

__device__ __forceinline__ unsigned pack_h2(float a, float b) {
    __half2 h = __floats2half2_rn(a, b);
    return *(unsigned*)&h;
}
__device__ __forceinline__ float2 unpack_h2(unsigned v) {
    __half2 h = *(__half2*)&v;
    return __half22float2(h);
}

// packed f32x2 helpers (sm_103a FFMA2; only reachable via PTX fma.rn.f32x2)
__device__ __forceinline__ u64 pk2(float v) {
    u64 r; asm("mov.b64 %0, {%1, %1};" : "=l"(r) : "f"(v)); return r;
}
__device__ __forceinline__ void fma2(u64& acc, u64 a, u64 b) {
    asm("fma.rn.f32x2 %0, %1, %2, %0;" : "+l"(acc) : "l"(a), "l"(b));
}
__device__ __forceinline__ void unpk2(u64 v, float& lo, float& hi) {
    asm("mov.b64 {%0, %1}, %2;" : "=f"(lo), "=f"(hi) : "l"(v));
}

// ---------------- CSR build (self-cleaning; no init kernel) ----------------
__global__ void k_deg(const int* __restrict__ dst, int nE) {
    int e = blockIdx.x * blockDim.x + threadIdx.x;
    if (e < nE) atomicAdd(&g_degi[dst[e]], 1);
}

// single-kernel CSR ranges (ticket-counter scan; region order irrelevant)
// + fused prep: dinv + u1 = fp16(x * dinv). Re-zeros g_degi for next launch.
__global__ void __launch_bounds__(256) k_scanprep(const float* __restrict__ x) {
    __shared__ int sh[256];
    __shared__ float sdinv[256];
    __shared__ int sbase;
    int tid = threadIdx.x;
    int i = blockIdx.x * 256 + tid;
    int deg = 0;
    if (i < NN) {
        deg = g_degi[i];
        g_degi[i] = 0;                       // restore zeros for next launch
    }
    sh[tid] = deg;
    __syncthreads();
    #pragma unroll
    for (int off = 1; off < 256; off <<= 1) {
        int t = (tid >= off) ? sh[tid - off] : 0;
        __syncthreads();
        sh[tid] += t;
        __syncthreads();
    }
    if (tid == 255) sbase = atomicAdd(&g_counter, sh[255]);
    float d = rsqrtf((float)(deg + 1));      // +1 self loop
    sdinv[tid] = d;
    __syncthreads();
    if (i < NN) {
        int end = sbase + sh[tid];
        g_end[i] = end;
        g_start[i] = end - deg;
        g_cur[i] = end - deg;
        g_dinv[i] = d;
    }
    // u1 staging: 8 uint4 per node (8 ch each)
    int base = blockIdx.x * 2048;            // 256 nodes * 8 uint4
    #pragma unroll
    for (int q = 0; q < 8; q++) {
        int idx = base + q * 256 + tid;      // uint4 index
        if (idx < NN * 8) {
            float dd = sdinv[(idx >> 3) - blockIdx.x * 256];
            float4 va = __ldg((const float4*)x + idx * 2);
            float4 vb = __ldg((const float4*)x + idx * 2 + 1);
            g_u1[idx] = make_uint4(pack_h2(va.x * dd, va.y * dd),
                                   pack_h2(va.z * dd, va.w * dd),
                                   pack_h2(vb.x * dd, vb.y * dd),
                                   pack_h2(vb.z * dd, vb.w * dd));
        }
    }
}

// 2 edges per thread (strided halves) for MLP; resets ticket counter.
__global__ void k_fill(const int* __restrict__ src, const int* __restrict__ dst,
                       int nE, int nHalf) {
    int e = blockIdx.x * blockDim.x + threadIdx.x;
    if (e == 0) g_counter = 0;               // restore ticket for next launch
    if (e < nHalf) {
        int d0 = __ldg(&dst[e]);
        int s0 = __ldg(&src[e]);
        int e1 = e + nHalf;
        int p0 = atomicAdd(&g_cur[d0], 1);
        if (e1 < nE) {
            int d1 = __ldg(&dst[e1]);
            int s1 = __ldg(&src[e1]);
            int p1 = atomicAdd(&g_cur[d1], 1);
            g_csr[p1] = s1;
        }
        g_csr[p0] = s0;
    }
}

// ---------------- gather (CSR, 8 lanes/node, 8 ch/lane, fp16 msgs, uint4 loads) ----
// MODE 2 accumulates BN stats of h2 = dinv*acc2 + b2 into g_stats[512..]
// MODE 3 writes final output. grid: NN*8/320 = 1250 blocks exactly.
template <int MODE>
__global__ void __launch_bounds__(320) k_gather(float* __restrict__ out,
                                                const float* __restrict__ bp) {
    __shared__ float ssum[64];
    __shared__ float ssq[64];
    int tid = threadIdx.x;
    if (MODE == 2) {
        if (tid < 64) ssum[tid] = 0.f;
        else if (tid < 128) ssq[tid - 64] = 0.f;
        __syncthreads();
    }
    int t = blockIdx.x * 320 + tid;          // uint4 slot: [0, NN*8)
    int g = t >> 3, lane = t & 7;
    const uint4* u = (MODE == 2) ? g_u2 : g_u3;

    float acc[8];
    {   // self-loop term
        uint4 r = __ldg(u + t);
        float2 p0 = unpack_h2(r.x), p1 = unpack_h2(r.y);
        float2 p2 = unpack_h2(r.z), p3 = unpack_h2(r.w);
        acc[0] = p0.x; acc[1] = p0.y; acc[2] = p1.x; acc[3] = p1.y;
        acc[4] = p2.x; acc[5] = p2.y; acc[6] = p3.x; acc[7] = p3.y;
    }
    int j = __ldg(&g_start[g]);
    int end = __ldg(&g_end[g]);
    for (; j + 3 < end; j += 4) {
        int s0 = __ldg(&g_csr[j]);
        int s1 = __ldg(&g_csr[j + 1]);
        int s2 = __ldg(&g_csr[j + 2]);
        int s3 = __ldg(&g_csr[j + 3]);
        uint4 r0 = __ldg(u + s0 * 8 + lane);
        uint4 r1 = __ldg(u + s1 * 8 + lane);
        uint4 r2 = __ldg(u + s2 * 8 + lane);
        uint4 r3 = __ldg(u + s3 * 8 + lane);
        float2 q0, q1;
        q0 = unpack_h2(r0.x); q1 = unpack_h2(r1.x);
        acc[0] += q0.x + q1.x; acc[1] += q0.y + q1.y;
        q0 = unpack_h2(r0.y); q1 = unpack_h2(r1.y);
        acc[2] += q0.x + q1.x; acc[3] += q0.y + q1.y;
        q0 = unpack_h2(r0.z); q1 = unpack_h2(r1.z);
        acc[4] += q0.x + q1.x; acc[5] += q0.y + q1.y;
        q0 = unpack_h2(r0.w); q1 = unpack_h2(r1.w);
        acc[6] += q0.x + q1.x; acc[7] += q0.y + q1.y;
        q0 = unpack_h2(r2.x); q1 = unpack_h2(r3.x);
        acc[0] += q0.x + q1.x; acc[1] += q0.y + q1.y;
        q0 = unpack_h2(r2.y); q1 = unpack_h2(r3.y);
        acc[2] += q0.x + q1.x; acc[3] += q0.y + q1.y;
        q0 = unpack_h2(r2.z); q1 = unpack_h2(r3.z);
        acc[4] += q0.x + q1.x; acc[5] += q0.y + q1.y;
        q0 = unpack_h2(r2.w); q1 = unpack_h2(r3.w);
        acc[6] += q0.x + q1.x; acc[7] += q0.y + q1.y;
    }
    for (; j < end; j++) {
        int s0 = __ldg(&g_csr[j]);
        uint4 r0 = __ldg(u + s0 * 8 + lane);
        float2 p0 = unpack_h2(r0.x), p1 = unpack_h2(r0.y);
        float2 p2 = unpack_h2(r0.z), p3 = unpack_h2(r0.w);
        acc[0] += p0.x; acc[1] += p0.y; acc[2] += p1.x; acc[3] += p1.y;
        acc[4] += p2.x; acc[5] += p2.y; acc[6] += p3.x; acc[7] += p3.y;
    }

    if (MODE == 2) {
        ((float4*)g_acc2)[t * 2]     = make_float4(acc[0], acc[1], acc[2], acc[3]);
        ((float4*)g_acc2)[t * 2 + 1] = make_float4(acc[4], acc[5], acc[6], acc[7]);
        // fused BN stats of h2 = dinv*acc + b2
        float d = g_dinv[g];
        float4 ba = __ldg((const float4*)bp + lane * 2);
        float4 bb = __ldg((const float4*)bp + lane * 2 + 1);
        float v[8], q[8];
        v[0] = fmaf(acc[0], d, ba.x); v[1] = fmaf(acc[1], d, ba.y);
        v[2] = fmaf(acc[2], d, ba.z); v[3] = fmaf(acc[3], d, ba.w);
        v[4] = fmaf(acc[4], d, bb.x); v[5] = fmaf(acc[5], d, bb.y);
        v[6] = fmaf(acc[6], d, bb.z); v[7] = fmaf(acc[7], d, bb.w);
        #pragma unroll
        for (int c = 0; c < 8; c++) q[c] = v[c] * v[c];
        #pragma unroll
        for (int c = 0; c < 8; c++) {
            v[c] += __shfl_xor_sync(0xffffffffu, v[c], 8);
            v[c] += __shfl_xor_sync(0xffffffffu, v[c], 16);
            q[c] += __shfl_xor_sync(0xffffffffu, q[c], 8);
            q[c] += __shfl_xor_sync(0xffffffffu, q[c], 16);
        }
        if ((tid & 31) < 8) {
            #pragma unroll
            for (int c = 0; c < 8; c++) {
                atomicAdd(&ssum[lane * 8 + c], v[c]);
                atomicAdd(&ssq[lane * 8 + c], q[c]);
            }
        }
        __syncthreads();
        if (tid < 64) {
            atomicAdd(&g_stats[512 + tid], ssum[tid]);
            atomicAdd(&g_stats[576 + tid], ssq[tid]);
        }
    } else {
        float d = g_dinv[g];
        float4 ba = __ldg((const float4*)bp + lane * 2);
        float4 bb = __ldg((const float4*)bp + lane * 2 + 1);
        ((float4*)out)[t * 2] = make_float4(fmaf(acc[0], d, ba.x), fmaf(acc[1], d, ba.y),
                                            fmaf(acc[2], d, ba.z), fmaf(acc[3], d, ba.w));
        ((float4*)out)[t * 2 + 1] = make_float4(fmaf(acc[4], d, bb.x), fmaf(acc[5], d, bb.y),
                                                fmaf(acc[6], d, bb.z), fmaf(acc[7], d, bb.w));
    }
}

// ---------------- fused GEMM (FFMA2 packed-f32x2 inner loop) ----------------
// MODE 1: FUSED GATHER: in = dinv * (CSR-sum of u1) (64, fp16 Is tile) -> W1 -> +b1
//         -> h1(fp16) + BN stats (p0=b1)
// MODE 2: in = leaky(fp16(h1)*scale1+shift1) (128) -> W2 -> *dinv -> u2 fp16
// MODE 3: in = leaky((dinv*acc2)*sc2+sh2) (64) -> W3 -> *dinv -> u3 fp16 (inline final2)
template <int K, int NC, int RPT, int MODE>
__global__ void __launch_bounds__(256) k_gemm(const float* __restrict__ Wg,
                                              const float* __restrict__ p0,
                                              const float* __restrict__ p1,
                                              const float* __restrict__ p2) {
    constexpr int R = 16 * RPT;
    constexpr int CPT = NC / 16;
    constexpr int CP2 = CPT / 2;
    constexpr int KQ = K / 4;
    __shared__ float Ws[K * NC];
    // MODE 1 stores the input tile as half2 (R*K/2 floats); modes 2/3 fp32 (R*K)
    __shared__ float Is[MODE == 1 ? R * K / 2 : R * K];
    __shared__ float s_sc[MODE == 3 ? 64 : 1];
    __shared__ float s_sh[MODE == 3 ? 64 : 1];

    const int tid = threadIdx.x;
    const int row0 = blockIdx.x * R;

    if (MODE == 3) {
        if (tid < 64) {
            float mean = g_stats[512 + tid] * (1.0f / NN);
            float var = g_stats[576 + tid] * (1.0f / NN) - mean * mean;
            float sc = rsqrtf(var + EPS_BN) * __ldg(&p0[tid]);
            s_sc[tid] = sc;
            s_sh[tid] = __ldg(&p1[tid]) + (__ldg(&p2[tid]) - mean) * sc;
        }
        __syncthreads();
    }

    {
        const float4* Wg4 = (const float4*)Wg;
        float4* Ws4 = (float4*)Ws;
        #pragma unroll
        for (int i = tid; i < K * NC / 4; i += 256) Ws4[i] = __ldg(Wg4 + i);
    }

    if (MODE == 1) {
        // fused gather staging: 4 threads per row, 16 channels each (2 uint4 slots)
        int rloc = tid >> 2;          // 0..63
        int seg = tid & 3;            // 0..3
        int gr = row0 + rloc;
        float av[16];
        #pragma unroll
        for (int c = 0; c < 16; c++) av[c] = 0.f;
        if (gr < NN) {
            const uint4* up = g_u1 + seg * 2;
            {   // self term
                uint4 ra = __ldg(up + gr * 8);
                uint4 rb = __ldg(up + gr * 8 + 1);
                float2 p;
                p = unpack_h2(ra.x); av[0] = p.x; av[1] = p.y;
                p = unpack_h2(ra.y); av[2] = p.x; av[3] = p.y;
                p = unpack_h2(ra.z); av[4] = p.x; av[5] = p.y;
                p = unpack_h2(ra.w); av[6] = p.x; av[7] = p.y;
                p = unpack_h2(rb.x); av[8] = p.x; av[9] = p.y;
                p = unpack_h2(rb.y); av[10] = p.x; av[11] = p.y;
                p = unpack_h2(rb.z); av[12] = p.x; av[13] = p.y;
                p = unpack_h2(rb.w); av[14] = p.x; av[15] = p.y;
            }
            int j = __ldg(&g_start[gr]);
            int end = __ldg(&g_end[gr]);
            for (; j + 1 < end; j += 2) {
                int s0 = __ldg(&g_csr[j]);
                int s1 = __ldg(&g_csr[j + 1]);
                uint4 ra = __ldg(up + s0 * 8);
                uint4 rb = __ldg(up + s0 * 8 + 1);
                uint4 rc = __ldg(up + s1 * 8);
                uint4 rd = __ldg(up + s1 * 8 + 1);
                float2 p, q;
                p = unpack_h2(ra.x); q = unpack_h2(rc.x); av[0] += p.x + q.x; av[1] += p.y + q.y;
                p = unpack_h2(ra.y); q = unpack_h2(rc.y); av[2] += p.x + q.x; av[3] += p.y + q.y;
                p = unpack_h2(ra.z); q = unpack_h2(rc.z); av[4] += p.x + q.x; av[5] += p.y + q.y;
                p = unpack_h2(ra.w); q = unpack_h2(rc.w); av[6] += p.x + q.x; av[7] += p.y + q.y;
                p = unpack_h2(rb.x); q = unpack_h2(rd.x); av[8] += p.x + q.x; av[9] += p.y + q.y;
                p = unpack_h2(rb.y); q = unpack_h2(rd.y); av[10] += p.x + q.x; av[11] += p.y + q.y;
                p = unpack_h2(rb.z); q = unpack_h2(rd.z); av[12] += p.x + q.x; av[13] += p.y + q.y;
                p = unpack_h2(rb.w); q = unpack_h2(rd.w); av[14] += p.x + q.x; av[15] += p.y + q.y;
            }
            if (j < end) {
                int s0 = __ldg(&g_csr[j]);
                uint4 ra = __ldg(up + s0 * 8);
                uint4 rb = __ldg(up + s0 * 8 + 1);
                float2 p;
                p = unpack_h2(ra.x); av[0] += p.x; av[1] += p.y;
                p = unpack_h2(ra.y); av[2] += p.x; av[3] += p.y;
                p = unpack_h2(ra.z); av[4] += p.x; av[5] += p.y;
                p = unpack_h2(ra.w); av[6] += p.x; av[7] += p.y;
                p = unpack_h2(rb.x); av[8] += p.x; av[9] += p.y;
                p = unpack_h2(rb.y); av[10] += p.x; av[11] += p.y;
                p = unpack_h2(rb.z); av[12] += p.x; av[13] += p.y;
                p = unpack_h2(rb.w); av[14] += p.x; av[15] += p.y;
            }
            float d = __ldg((const float*)&g_dinv[gr]);
            #pragma unroll
            for (int c = 0; c < 16; c++) av[c] *= d;
        }
        // pack back to half2: per row 32 half2 words; seg covers words [seg*8, seg*8+8)
        uint4* dst4 = (uint4*)((unsigned*)Is + rloc * 32 + seg * 8);
        dst4[0] = make_uint4(pack_h2(av[0], av[1]), pack_h2(av[2], av[3]),
                             pack_h2(av[4], av[5]), pack_h2(av[6], av[7]));
        dst4[1] = make_uint4(pack_h2(av[8], av[9]), pack_h2(av[10], av[11]),
                             pack_h2(av[12], av[13]), pack_h2(av[14], av[15]));
    } else {
        float4* Is4 = (float4*)Is;
        #pragma unroll
        for (int i = tid; i < R * KQ; i += 256) {
            int r = i / KQ, kq = i % KQ;
            int gr = row0 + r;
            float4 v = make_float4(0.f, 0.f, 0.f, 0.f);
            if (gr < NN) {
                if (MODE == 2) {
                    uint2 hv = __ldg((const uint2*)g_h1h + gr * 32 + kq);
                    float2 ha = unpack_h2(hv.x), hb = unpack_h2(hv.y);
                    float4 sc = __ldg((const float4*)(g_stats + 256) + kq);
                    float4 sh = __ldg((const float4*)(g_stats + 384) + kq);
                    v.x = lrelu(fmaf(ha.x, sc.x, sh.x));
                    v.y = lrelu(fmaf(ha.y, sc.y, sh.y));
                    v.z = lrelu(fmaf(hb.x, sc.z, sh.z));
                    v.w = lrelu(fmaf(hb.y, sc.w, sh.w));
                } else {
                    float4 a = __ldg((const float4*)g_acc2 + gr * 16 + kq);
                    float d = __ldg((const float*)&g_dinv[gr]);
                    float4 sc = *(const float4*)(s_sc + kq * 4);
                    float4 sh = *(const float4*)(s_sh + kq * 4);
                    v.x = lrelu(fmaf(a.x * d, sc.x, sh.x));
                    v.y = lrelu(fmaf(a.y * d, sc.y, sh.y));
                    v.z = lrelu(fmaf(a.z * d, sc.z, sh.z));
                    v.w = lrelu(fmaf(a.w * d, sc.w, sh.w));
                }
            }
            Is4[i] = v;
        }
    }
    __syncthreads();

    const int ct = tid & 15, rt = tid >> 4;
    u64 accp[RPT][CP2];
    #pragma unroll
    for (int j = 0; j < RPT; j++)
        #pragma unroll
        for (int c = 0; c < CP2; c++) accp[j][c] = 0ull;

    const float* isbase_f = Is + (rt * RPT) * K;              // modes 2/3
    const unsigned* isbase_h = (const unsigned*)Is + (rt * RPT) * 32;  // mode 1
    #pragma unroll 4
    for (int k4 = 0; k4 < K / 4; ++k4) {
        float a[RPT][4];
        #pragma unroll
        for (int j = 0; j < RPT; j++) {
            if (MODE == 1) {
                uint2 t2 = *(const uint2*)(isbase_h + j * 32 + k4 * 2);
                float2 lo = unpack_h2(t2.x), hi = unpack_h2(t2.y);
                a[j][0] = lo.x; a[j][1] = lo.y; a[j][2] = hi.x; a[j][3] = hi.y;
            } else {
                float4 t4 = *(const float4*)(isbase_f + j * K + k4 * 4);
                a[j][0] = t4.x; a[j][1] = t4.y; a[j][2] = t4.z; a[j][3] = t4.w;
            }
        }
        #pragma unroll
        for (int kk = 0; kk < 4; kk++) {
            // W pairs come packed-for-free from shared: adjacent cols = one u64
            u64 w[CP2];
            if (CP2 == 4) {
                ulonglong2 w2a = *(const ulonglong2*)(Ws + (k4 * 4 + kk) * NC + ct * CPT);
                ulonglong2 w2b = *(const ulonglong2*)(Ws + (k4 * 4 + kk) * NC + ct * CPT + 4);
                w[0] = w2a.x; w[1] = w2a.y; w[2] = w2b.x; w[3] = w2b.y;
            } else {
                ulonglong2 w2a = *(const ulonglong2*)(Ws + (k4 * 4 + kk) * NC + ct * CPT);
                w[0] = w2a.x; w[1] = w2a.y;
            }
            #pragma unroll
            for (int j = 0; j < RPT; j++) {
                u64 ap = pk2(a[j][kk]);
                #pragma unroll
                for (int c = 0; c < CP2; c++) fma2(accp[j][c], ap, w[c]);
            }
        }
    }

    // unpack accumulators to fp32
    float acc[RPT][CPT];
    #pragma unroll
    for (int j = 0; j < RPT; j++)
        #pragma unroll
        for (int c = 0; c < CP2; c++)
            unpk2(accp[j][c], acc[j][2 * c], acc[j][2 * c + 1]);

    if (MODE == 1) {
        float bl[CPT];
        #pragma unroll
        for (int c = 0; c < CPT; c++) bl[c] = __ldg(&p0[ct * CPT + c]);
        #pragma unroll
        for (int j = 0; j < RPT; j++) {
            int gr = row0 + rt * RPT + j;
            if (gr < NN) {
                #pragma unroll
                for (int c = 0; c < CPT; c++) acc[j][c] += bl[c];
                // h1 stored fp16: CPT=8 floats -> 4 half2 = one uint4 per (row, ct)
                g_h1h[gr * 16 + ct] = make_uint4(
                    pack_h2(acc[j][0], acc[j][1]), pack_h2(acc[j][2], acc[j][3]),
                    pack_h2(acc[j][4], acc[j][5]), pack_h2(acc[j][6], acc[j][7]));
            } else {
                #pragma unroll
                for (int c = 0; c < CPT; c++) acc[j][c] = 0.f;
            }
        }
        __syncthreads();
        float* ssum = Is;
        float* ssq = Is + NC;
        if (tid < 2 * NC) Is[tid] = 0.f;
        __syncthreads();
        #pragma unroll
        for (int c = 0; c < CPT; c++) {
            float sv = 0.f, sq = 0.f;
            #pragma unroll
            for (int j = 0; j < RPT; j++) { sv += acc[j][c]; sq += acc[j][c] * acc[j][c]; }
            atomicAdd(&ssum[ct * CPT + c], sv);
            atomicAdd(&ssq[ct * CPT + c], sq);
        }
        __syncthreads();
        if (tid < NC) {
            atomicAdd(&g_stats[tid], ssum[tid]);
            atomicAdd(&g_stats[128 + tid], ssq[tid]);
        }
    } else {
        uint2* o0 = (MODE == 2) ? (uint2*)g_u2 : (uint2*)g_u3;
        #pragma unroll
        for (int j = 0; j < RPT; j++) {
            int gr = row0 + rt * RPT + j;
            if (gr >= NN) continue;
            float d = __ldg((const float*)&g_dinv[gr]);
            o0[gr * 16 + ct] = make_uint2(pack_h2(acc[j][0] * d, acc[j][1] * d),
                                          pack_h2(acc[j][2] * d, acc[j][3] * d));
        }
    }
}

// consumes stats[0..255] -> scale1/shift1; zeros [0..255] (next launch's gemm1)
// and [512..639] (this launch's gather2 accumulation).
__global__ void k_final1(const float* __restrict__ g1, const float* __restrict__ be1) {
    int c = threadIdx.x;  // 128
    float s1 = g_stats[c];
    float s2 = g_stats[128 + c];
    float mean = s1 * (1.0f / NN);
    float var = s2 * (1.0f / NN) - mean * mean;
    float sc = rsqrtf(var + EPS_BN) * __ldg(&g1[c]);
    g_stats[256 + c] = sc;
    g_stats[384 + c] = __ldg(&be1[c]) - mean * sc;
    g_stats[c] = 0.f;
    g_stats[128 + c] = 0.f;
    g_stats[512 + c] = 0.f;
}

// ---------------- launcher ----------------
extern "C" void kernel_launch(void* const* d_in, const int* in_sizes, int n_in,
                              void* d_out, int out_size) {
    const float* x  = (const float*)d_in[0];
    const int* ei   = (const int*)d_in[1];
    const float* W1 = (const float*)d_in[2];
    const float* b1 = (const float*)d_in[3];
    const float* g1 = (const float*)d_in[4];
    const float* be1= (const float*)d_in[5];
    const float* W2 = (const float*)d_in[6];
    const float* b2 = (const float*)d_in[7];
    const float* g2 = (const float*)d_in[8];
    const float* be2= (const float*)d_in[9];
    const float* W3 = (const float*)d_in[10];
    const float* b3 = (const float*)d_in[11];

    const int nE = in_sizes[1] / 2;
    const int* src = ei;
    const int* dst = ei + nE;
    const int nHalf = (nE + 1) / 2;

    // CSR build + prep (self-cleaning; no init kernel)
    k_deg<<<(nE + 255) / 256, 256>>>(dst, nE);
    k_scanprep<<<NBLK, 256>>>(x);
    k_fill<<<(nHalf + 255) / 256, 256>>>(src, dst, nE, nHalf);

    // layer 1: gather fused into gemm1 (A(xW) == (Ax)W)
    k_gemm<64, 128, 4, 1><<<(NN + 63) / 64, 256>>>(W1, b1, nullptr, nullptr);
    k_final1<<<1, 128>>>(g1, be1);

    // layer 2 (gather fuses BN stats of h2)
    k_gemm<128, 64, 2, 2><<<(NN + 31) / 32, 256>>>(W2, nullptr, nullptr, nullptr);
    k_gather<2><<<NN * 8 / 320, 320>>>(nullptr, b2);

    // layer 3 (gemm inlines final2)
    k_gemm<64, 64, 4, 3><<<(NN + 63) / 64, 256>>>(W3, g2, be2, b2);
    k_gather<3><<<NN * 8 / 320, 320>>>((float*)d_out, b3);
}

// round 14
// speedup vs baseline: 1.0736x; 1.0736x over previous
#include <cuda_runtime.h>
#include <cuda_fp16.h>
#include <math.h>

#define NN 50000
#define NBLK 196          // ceil(NN/256)
#define EPS_BN 1e-5f
#define SLOPE 0.01f

// ---------------- scratch (static device memory; no allocs) ----------------
__device__ int   g_degi[NN];
__device__ int   g_counter;
__device__ int   g_start[NN];
__device__ int   g_end[NN];
__device__ int   g_cur[NN];
__device__ int   g_csr[800000];
__device__ float g_dinv[NN];
// fp16 message buffers: 64 ch = 8 uint4 per node (8 ch per uint4 as 4x half2)
__device__ uint4 g_u1[NN * 8];
__device__ uint4 g_u2[NN * 8];
__device__ uint4 g_u3[NN * 8];
// h1 in fp16: 128 ch = 16 uint4 per node
__device__ uint4 g_h1h[NN * 16];
__device__ float g_acc2[NN * 64];
// stats layout:
// [0:128) sum1  [128:256) sumsq1  [256:384) scale1  [384:512) shift1
// [512:576) sum2 [576:640) sumsq2
__device__ float g_stats[1024];

__device__ __forceinline__ float lrelu(float v) { return v > 0.f ? v : SLOPE * v; }

__device__ __forceinline__ unsigned pack_h2(float a, float b) {
    __half2 h = __floats2half2_rn(a, b);
    return *(unsigned*)&h;
}
__device__ __forceinline__ float2 unpack_h2(unsigned v) {
    __half2 h = *(__half2*)&v;
    return __half22float2(h);
}

// ---------------- CSR build (self-cleaning; no init kernel) ----------------
__global__ void k_deg(const int* __restrict__ dst, int nE) {
    int e = blockIdx.x * blockDim.x + threadIdx.x;
    if (e < nE) atomicAdd(&g_degi[dst[e]], 1);
}

// single-kernel CSR ranges (ticket-counter scan; region order irrelevant)
// + fused prep: dinv + u1 = fp16(x * dinv). Re-zeros g_degi for next launch.
__global__ void __launch_bounds__(256) k_scanprep(const float* __restrict__ x) {
    __shared__ int sh[256];
    __shared__ float sdinv[256];
    __shared__ int sbase;
    int tid = threadIdx.x;
    int i = blockIdx.x * 256 + tid;
    int deg = 0;
    if (i < NN) {
        deg = g_degi[i];
        g_degi[i] = 0;                       // restore zeros for next launch
    }
    sh[tid] = deg;
    __syncthreads();
    #pragma unroll
    for (int off = 1; off < 256; off <<= 1) {
        int t = (tid >= off) ? sh[tid - off] : 0;
        __syncthreads();
        sh[tid] += t;
        __syncthreads();
    }
    if (tid == 255) sbase = atomicAdd(&g_counter, sh[255]);
    float d = rsqrtf((float)(deg + 1));      // +1 self loop
    sdinv[tid] = d;
    __syncthreads();
    if (i < NN) {
        int end = sbase + sh[tid];
        g_end[i] = end;
        g_start[i] = end - deg;
        g_cur[i] = end - deg;
        g_dinv[i] = d;
    }
    // u1 staging: 8 uint4 per node (8 ch each)
    int base = blockIdx.x * 2048;            // 256 nodes * 8 uint4
    #pragma unroll
    for (int q = 0; q < 8; q++) {
        int idx = base + q * 256 + tid;      // uint4 index
        if (idx < NN * 8) {
            float dd = sdinv[(idx >> 3) - blockIdx.x * 256];
            float4 va = __ldg((const float4*)x + idx * 2);
            float4 vb = __ldg((const float4*)x + idx * 2 + 1);
            g_u1[idx] = make_uint4(pack_h2(va.x * dd, va.y * dd),
                                   pack_h2(va.z * dd, va.w * dd),
                                   pack_h2(vb.x * dd, vb.y * dd),
                                   pack_h2(vb.z * dd, vb.w * dd));
        }
    }
}

// 2 edges per thread (strided halves) for MLP; resets ticket counter.
__global__ void k_fill(const int* __restrict__ src, const int* __restrict__ dst,
                       int nE, int nHalf) {
    int e = blockIdx.x * blockDim.x + threadIdx.x;
    if (e == 0) g_counter = 0;               // restore ticket for next launch
    if (e < nHalf) {
        int d0 = __ldg(&dst[e]);
        int s0 = __ldg(&src[e]);
        int e1 = e + nHalf;
        int p0 = atomicAdd(&g_cur[d0], 1);
        if (e1 < nE) {
            int d1 = __ldg(&dst[e1]);
            int s1 = __ldg(&src[e1]);
            int p1 = atomicAdd(&g_cur[d1], 1);
            g_csr[p1] = s1;
        }
        g_csr[p0] = s0;
    }
}

// ---------------- gather (CSR, 8 lanes/node, 8 ch/lane, fp16 msgs, uint4 loads) ----
// MODE 2 accumulates BN stats of h2 = dinv*acc2 + b2 into g_stats[512..]
// MODE 3 writes final output. grid: NN*8/320 = 1250 blocks exactly.
template <int MODE>
__global__ void __launch_bounds__(320) k_gather(float* __restrict__ out,
                                                const float* __restrict__ bp) {
    __shared__ float ssum[64];
    __shared__ float ssq[64];
    int tid = threadIdx.x;
    if (MODE == 2) {
        if (tid < 64) ssum[tid] = 0.f;
        else if (tid < 128) ssq[tid - 64] = 0.f;
        __syncthreads();
    }
    int t = blockIdx.x * 320 + tid;          // uint4 slot: [0, NN*8)
    int g = t >> 3, lane = t & 7;
    const uint4* u = (MODE == 2) ? g_u2 : g_u3;

    float acc[8];
    {   // self-loop term
        uint4 r = __ldg(u + t);
        float2 p0 = unpack_h2(r.x), p1 = unpack_h2(r.y);
        float2 p2 = unpack_h2(r.z), p3 = unpack_h2(r.w);
        acc[0] = p0.x; acc[1] = p0.y; acc[2] = p1.x; acc[3] = p1.y;
        acc[4] = p2.x; acc[5] = p2.y; acc[6] = p3.x; acc[7] = p3.y;
    }
    int j = __ldg(&g_start[g]);
    int end = __ldg(&g_end[g]);
    for (; j + 3 < end; j += 4) {
        int s0 = __ldg(&g_csr[j]);
        int s1 = __ldg(&g_csr[j + 1]);
        int s2 = __ldg(&g_csr[j + 2]);
        int s3 = __ldg(&g_csr[j + 3]);
        uint4 r0 = __ldg(u + s0 * 8 + lane);
        uint4 r1 = __ldg(u + s1 * 8 + lane);
        uint4 r2 = __ldg(u + s2 * 8 + lane);
        uint4 r3 = __ldg(u + s3 * 8 + lane);
        float2 q0, q1;
        q0 = unpack_h2(r0.x); q1 = unpack_h2(r1.x);
        acc[0] += q0.x + q1.x; acc[1] += q0.y + q1.y;
        q0 = unpack_h2(r0.y); q1 = unpack_h2(r1.y);
        acc[2] += q0.x + q1.x; acc[3] += q0.y + q1.y;
        q0 = unpack_h2(r0.z); q1 = unpack_h2(r1.z);
        acc[4] += q0.x + q1.x; acc[5] += q0.y + q1.y;
        q0 = unpack_h2(r0.w); q1 = unpack_h2(r1.w);
        acc[6] += q0.x + q1.x; acc[7] += q0.y + q1.y;
        q0 = unpack_h2(r2.x); q1 = unpack_h2(r3.x);
        acc[0] += q0.x + q1.x; acc[1] += q0.y + q1.y;
        q0 = unpack_h2(r2.y); q1 = unpack_h2(r3.y);
        acc[2] += q0.x + q1.x; acc[3] += q0.y + q1.y;
        q0 = unpack_h2(r2.z); q1 = unpack_h2(r3.z);
        acc[4] += q0.x + q1.x; acc[5] += q0.y + q1.y;
        q0 = unpack_h2(r2.w); q1 = unpack_h2(r3.w);
        acc[6] += q0.x + q1.x; acc[7] += q0.y + q1.y;
    }
    for (; j < end; j++) {
        int s0 = __ldg(&g_csr[j]);
        uint4 r0 = __ldg(u + s0 * 8 + lane);
        float2 p0 = unpack_h2(r0.x), p1 = unpack_h2(r0.y);
        float2 p2 = unpack_h2(r0.z), p3 = unpack_h2(r0.w);
        acc[0] += p0.x; acc[1] += p0.y; acc[2] += p1.x; acc[3] += p1.y;
        acc[4] += p2.x; acc[5] += p2.y; acc[6] += p3.x; acc[7] += p3.y;
    }

    if (MODE == 2) {
        ((float4*)g_acc2)[t * 2]     = make_float4(acc[0], acc[1], acc[2], acc[3]);
        ((float4*)g_acc2)[t * 2 + 1] = make_float4(acc[4], acc[5], acc[6], acc[7]);
        // fused BN stats of h2 = dinv*acc + b2
        float d = g_dinv[g];
        float4 ba = __ldg((const float4*)bp + lane * 2);
        float4 bb = __ldg((const float4*)bp + lane * 2 + 1);
        float v[8], q[8];
        v[0] = fmaf(acc[0], d, ba.x); v[1] = fmaf(acc[1], d, ba.y);
        v[2] = fmaf(acc[2], d, ba.z); v[3] = fmaf(acc[3], d, ba.w);
        v[4] = fmaf(acc[4], d, bb.x); v[5] = fmaf(acc[5], d, bb.y);
        v[6] = fmaf(acc[6], d, bb.z); v[7] = fmaf(acc[7], d, bb.w);
        #pragma unroll
        for (int c = 0; c < 8; c++) q[c] = v[c] * v[c];
        #pragma unroll
        for (int c = 0; c < 8; c++) {
            v[c] += __shfl_xor_sync(0xffffffffu, v[c], 8);
            v[c] += __shfl_xor_sync(0xffffffffu, v[c], 16);
            q[c] += __shfl_xor_sync(0xffffffffu, q[c], 8);
            q[c] += __shfl_xor_sync(0xffffffffu, q[c], 16);
        }
        if ((tid & 31) < 8) {
            #pragma unroll
            for (int c = 0; c < 8; c++) {
                atomicAdd(&ssum[lane * 8 + c], v[c]);
                atomicAdd(&ssq[lane * 8 + c], q[c]);
            }
        }
        __syncthreads();
        if (tid < 64) {
            atomicAdd(&g_stats[512 + tid], ssum[tid]);
            atomicAdd(&g_stats[576 + tid], ssq[tid]);
        }
    } else {
        float d = g_dinv[g];
        float4 ba = __ldg((const float4*)bp + lane * 2);
        float4 bb = __ldg((const float4*)bp + lane * 2 + 1);
        ((float4*)out)[t * 2] = make_float4(fmaf(acc[0], d, ba.x), fmaf(acc[1], d, ba.y),
                                            fmaf(acc[2], d, ba.z), fmaf(acc[3], d, ba.w));
        ((float4*)out)[t * 2 + 1] = make_float4(fmaf(acc[4], d, bb.x), fmaf(acc[5], d, bb.y),
                                                fmaf(acc[6], d, bb.z), fmaf(acc[7], d, bb.w));
    }
}

// ---------------- layer-1 fused gather+GEMM (NC-split for occupancy) ----------------
// in = dinv * (CSR-sum of u1) (64, fp16 Is tile) -> W1 (two 64-col halves) -> +b1
// -> h1(fp16) + BN stats. smem 25KB, launch_bounds(256,4) -> 4 blocks/SM.
__global__ void __launch_bounds__(256, 4) k_gemm1(const float* __restrict__ Wg,
                                                  const float* __restrict__ bias) {
    __shared__ float Ws[64 * 64];        // 16KB: one NC-half
    __shared__ unsigned Ish[64 * 32];    // 8KB: 64 rows x 32 half2 words
    __shared__ float ssum[128];
    __shared__ float ssq[128];

    const int tid = threadIdx.x;
    const int row0 = blockIdx.x * 64;

    if (tid < 128) ssum[tid] = 0.f;
    else ssq[tid - 128] = 0.f;

    // ---- gather staging: 4 threads per row, 16 channels each (2 uint4 slots) ----
    {
        int rloc = tid >> 2;          // 0..63
        int seg = tid & 3;            // 0..3
        int gr = row0 + rloc;
        float av[16];
        #pragma unroll
        for (int c = 0; c < 16; c++) av[c] = 0.f;
        if (gr < NN) {
            const uint4* up = g_u1 + seg * 2;
            {   // self term
                uint4 ra = __ldg(up + gr * 8);
                uint4 rb = __ldg(up + gr * 8 + 1);
                float2 p;
                p = unpack_h2(ra.x); av[0] = p.x; av[1] = p.y;
                p = unpack_h2(ra.y); av[2] = p.x; av[3] = p.y;
                p = unpack_h2(ra.z); av[4] = p.x; av[5] = p.y;
                p = unpack_h2(ra.w); av[6] = p.x; av[7] = p.y;
                p = unpack_h2(rb.x); av[8] = p.x; av[9] = p.y;
                p = unpack_h2(rb.y); av[10] = p.x; av[11] = p.y;
                p = unpack_h2(rb.z); av[12] = p.x; av[13] = p.y;
                p = unpack_h2(rb.w); av[14] = p.x; av[15] = p.y;
            }
            int j = __ldg(&g_start[gr]);
            int end = __ldg(&g_end[gr]);
            for (; j + 1 < end; j += 2) {
                int s0 = __ldg(&g_csr[j]);
                int s1 = __ldg(&g_csr[j + 1]);
                uint4 ra = __ldg(up + s0 * 8);
                uint4 rb = __ldg(up + s0 * 8 + 1);
                uint4 rc = __ldg(up + s1 * 8);
                uint4 rd = __ldg(up + s1 * 8 + 1);
                float2 p, q;
                p = unpack_h2(ra.x); q = unpack_h2(rc.x); av[0] += p.x + q.x; av[1] += p.y + q.y;
                p = unpack_h2(ra.y); q = unpack_h2(rc.y); av[2] += p.x + q.x; av[3] += p.y + q.y;
                p = unpack_h2(ra.z); q = unpack_h2(rc.z); av[4] += p.x + q.x; av[5] += p.y + q.y;
                p = unpack_h2(ra.w); q = unpack_h2(rc.w); av[6] += p.x + q.x; av[7] += p.y + q.y;
                p = unpack_h2(rb.x); q = unpack_h2(rd.x); av[8] += p.x + q.x; av[9] += p.y + q.y;
                p = unpack_h2(rb.y); q = unpack_h2(rd.y); av[10] += p.x + q.x; av[11] += p.y + q.y;
                p = unpack_h2(rb.z); q = unpack_h2(rd.z); av[12] += p.x + q.x; av[13] += p.y + q.y;
                p = unpack_h2(rb.w); q = unpack_h2(rd.w); av[14] += p.x + q.x; av[15] += p.y + q.y;
            }
            if (j < end) {
                int s0 = __ldg(&g_csr[j]);
                uint4 ra = __ldg(up + s0 * 8);
                uint4 rb = __ldg(up + s0 * 8 + 1);
                float2 p;
                p = unpack_h2(ra.x); av[0] += p.x; av[1] += p.y;
                p = unpack_h2(ra.y); av[2] += p.x; av[3] += p.y;
                p = unpack_h2(ra.z); av[4] += p.x; av[5] += p.y;
                p = unpack_h2(ra.w); av[6] += p.x; av[7] += p.y;
                p = unpack_h2(rb.x); av[8] += p.x; av[9] += p.y;
                p = unpack_h2(rb.y); av[10] += p.x; av[11] += p.y;
                p = unpack_h2(rb.z); av[12] += p.x; av[13] += p.y;
                p = unpack_h2(rb.w); av[14] += p.x; av[15] += p.y;
            }
            float d = __ldg((const float*)&g_dinv[gr]);
            #pragma unroll
            for (int c = 0; c < 16; c++) av[c] *= d;
        }
        uint4* dst4 = (uint4*)(Ish + rloc * 32 + seg * 8);
        dst4[0] = make_uint4(pack_h2(av[0], av[1]), pack_h2(av[2], av[3]),
                             pack_h2(av[4], av[5]), pack_h2(av[6], av[7]));
        dst4[1] = make_uint4(pack_h2(av[8], av[9]), pack_h2(av[10], av[11]),
                             pack_h2(av[12], av[13]), pack_h2(av[14], av[15]));
    }

    const int ct = tid & 15, rt = tid >> 4;
    const unsigned* isbase = Ish + (rt * 4) * 32;
    const float4* Wg4 = (const float4*)Wg;    // 64 rows x 32 float4 (NC=128)
    float4* Ws4 = (float4*)Ws;

    #pragma unroll
    for (int h = 0; h < 2; h++) {
        if (h) __syncthreads();               // all reads of previous Ws done
        // stage W half: 64 x 64 floats = 1024 float4
        #pragma unroll
        for (int i = tid; i < 1024; i += 256) {
            int k = i >> 4, c4 = i & 15;
            Ws4[i] = __ldg(Wg4 + k * 32 + h * 16 + c4);
        }
        __syncthreads();

        float acc[4][4];
        #pragma unroll
        for (int j = 0; j < 4; j++)
            #pragma unroll
            for (int c = 0; c < 4; c++) acc[j][c] = 0.f;

        #pragma unroll 4
        for (int k4 = 0; k4 < 16; ++k4) {
            float a[4][4];
            #pragma unroll
            for (int j = 0; j < 4; j++) {
                uint2 t2 = *(const uint2*)(isbase + j * 32 + k4 * 2);
                float2 lo = unpack_h2(t2.x), hi = unpack_h2(t2.y);
                a[j][0] = lo.x; a[j][1] = lo.y; a[j][2] = hi.x; a[j][3] = hi.y;
            }
            #pragma unroll
            for (int kk = 0; kk < 4; kk++) {
                float4 w4 = *(const float4*)(Ws + (k4 * 4 + kk) * 64 + ct * 4);
                #pragma unroll
                for (int j = 0; j < 4; j++) {
                    acc[j][0] = fmaf(a[j][kk], w4.x, acc[j][0]);
                    acc[j][1] = fmaf(a[j][kk], w4.y, acc[j][1]);
                    acc[j][2] = fmaf(a[j][kk], w4.z, acc[j][2]);
                    acc[j][3] = fmaf(a[j][kk], w4.w, acc[j][3]);
                }
            }
        }

        // epilogue for this half: bias, fp16 h1 write, local stats
        float bl[4];
        #pragma unroll
        for (int c = 0; c < 4; c++) bl[c] = __ldg(&bias[h * 64 + ct * 4 + c]);
        #pragma unroll
        for (int j = 0; j < 4; j++) {
            int gr = row0 + rt * 4 + j;
            if (gr < NN) {
                #pragma unroll
                for (int c = 0; c < 4; c++) acc[j][c] += bl[c];
                ((uint2*)g_h1h)[gr * 32 + h * 16 + ct] =
                    make_uint2(pack_h2(acc[j][0], acc[j][1]),
                               pack_h2(acc[j][2], acc[j][3]));
            } else {
                #pragma unroll
                for (int c = 0; c < 4; c++) acc[j][c] = 0.f;
            }
        }
        #pragma unroll
        for (int c = 0; c < 4; c++) {
            float sv = 0.f, sq = 0.f;
            #pragma unroll
            for (int j = 0; j < 4; j++) { sv += acc[j][c]; sq += acc[j][c] * acc[j][c]; }
            atomicAdd(&ssum[h * 64 + ct * 4 + c], sv);
            atomicAdd(&ssq[h * 64 + ct * 4 + c], sq);
        }
    }
    __syncthreads();
    if (tid < 128) {
        atomicAdd(&g_stats[tid], ssum[tid]);
        atomicAdd(&g_stats[128 + tid], ssq[tid]);
    }
}

// ---------------- fused GEMM (modes 2/3, scalar FMA, R12-proven) ----------------
// MODE 2: in = leaky(fp16(h1)*scale1+shift1) (128) -> W2 -> *dinv -> u2 fp16
// MODE 3: in = leaky((dinv*acc2)*sc2+sh2) (64) -> W3 -> *dinv -> u3 fp16 (inline final2)
template <int K, int NC, int RPT, int MODE>
__global__ void __launch_bounds__(256) k_gemm(const float* __restrict__ Wg,
                                              const float* __restrict__ p0,
                                              const float* __restrict__ p1,
                                              const float* __restrict__ p2) {
    constexpr int R = 16 * RPT;
    constexpr int CPT = NC / 16;
    constexpr int KQ = K / 4;
    __shared__ float Ws[K * NC];
    __shared__ float Is[R * K];
    __shared__ float s_sc[MODE == 3 ? 64 : 1];
    __shared__ float s_sh[MODE == 3 ? 64 : 1];

    const int tid = threadIdx.x;
    const int row0 = blockIdx.x * R;

    if (MODE == 3) {
        if (tid < 64) {
            float mean = g_stats[512 + tid] * (1.0f / NN);
            float var = g_stats[576 + tid] * (1.0f / NN) - mean * mean;
            float sc = rsqrtf(var + EPS_BN) * __ldg(&p0[tid]);
            s_sc[tid] = sc;
            s_sh[tid] = __ldg(&p1[tid]) + (__ldg(&p2[tid]) - mean) * sc;
        }
        __syncthreads();
    }

    {
        const float4* Wg4 = (const float4*)Wg;
        float4* Ws4 = (float4*)Ws;
        #pragma unroll
        for (int i = tid; i < K * NC / 4; i += 256) Ws4[i] = __ldg(Wg4 + i);
    }
    {
        float4* Is4 = (float4*)Is;
        #pragma unroll
        for (int i = tid; i < R * KQ; i += 256) {
            int r = i / KQ, kq = i % KQ;
            int gr = row0 + r;
            float4 v = make_float4(0.f, 0.f, 0.f, 0.f);
            if (gr < NN) {
                if (MODE == 2) {
                    uint2 hv = __ldg((const uint2*)g_h1h + gr * 32 + kq);
                    float2 ha = unpack_h2(hv.x), hb = unpack_h2(hv.y);
                    float4 sc = __ldg((const float4*)(g_stats + 256) + kq);
                    float4 sh = __ldg((const float4*)(g_stats + 384) + kq);
                    v.x = lrelu(fmaf(ha.x, sc.x, sh.x));
                    v.y = lrelu(fmaf(ha.y, sc.y, sh.y));
                    v.z = lrelu(fmaf(hb.x, sc.z, sh.z));
                    v.w = lrelu(fmaf(hb.y, sc.w, sh.w));
                } else {
                    float4 a = __ldg((const float4*)g_acc2 + gr * 16 + kq);
                    float d = __ldg((const float*)&g_dinv[gr]);
                    float4 sc = *(const float4*)(s_sc + kq * 4);
                    float4 sh = *(const float4*)(s_sh + kq * 4);
                    v.x = lrelu(fmaf(a.x * d, sc.x, sh.x));
                    v.y = lrelu(fmaf(a.y * d, sc.y, sh.y));
                    v.z = lrelu(fmaf(a.z * d, sc.z, sh.z));
                    v.w = lrelu(fmaf(a.w * d, sc.w, sh.w));
                }
            }
            Is4[i] = v;
        }
    }
    __syncthreads();

    const int ct = tid & 15, rt = tid >> 4;
    float acc[RPT][CPT];
    #pragma unroll
    for (int j = 0; j < RPT; j++)
        #pragma unroll
        for (int c = 0; c < CPT; c++) acc[j][c] = 0.f;

    const float* isbase = Is + (rt * RPT) * K;
    #pragma unroll 4
    for (int k4 = 0; k4 < K / 4; ++k4) {
        float a[RPT][4];
        #pragma unroll
        for (int j = 0; j < RPT; j++) {
            float4 t4 = *(const float4*)(isbase + j * K + k4 * 4);
            a[j][0] = t4.x; a[j][1] = t4.y; a[j][2] = t4.z; a[j][3] = t4.w;
        }
        #pragma unroll
        for (int kk = 0; kk < 4; kk++) {
            float w[CPT];
            const float4* wr = (const float4*)(Ws + (k4 * 4 + kk) * NC + ct * CPT);
            #pragma unroll
            for (int q = 0; q < CPT / 4; q++) {
                float4 w4 = wr[q];
                w[q * 4 + 0] = w4.x; w[q * 4 + 1] = w4.y;
                w[q * 4 + 2] = w4.z; w[q * 4 + 3] = w4.w;
            }
            #pragma unroll
            for (int j = 0; j < RPT; j++)
                #pragma unroll
                for (int c = 0; c < CPT; c++)
                    acc[j][c] = fmaf(a[j][kk], w[c], acc[j][c]);
        }
    }

    uint2* o0 = (MODE == 2) ? (uint2*)g_u2 : (uint2*)g_u3;
    #pragma unroll
    for (int j = 0; j < RPT; j++) {
        int gr = row0 + rt * RPT + j;
        if (gr >= NN) continue;
        float d = __ldg((const float*)&g_dinv[gr]);
        o0[gr * 16 + ct] = make_uint2(pack_h2(acc[j][0] * d, acc[j][1] * d),
                                      pack_h2(acc[j][2] * d, acc[j][3] * d));
    }
}

// consumes stats[0..255] -> scale1/shift1; zeros [0..255] (next launch's gemm1)
// and [512..639] (this launch's gather2 accumulation).
__global__ void k_final1(const float* __restrict__ g1, const float* __restrict__ be1) {
    int c = threadIdx.x;  // 128
    float s1 = g_stats[c];
    float s2 = g_stats[128 + c];
    float mean = s1 * (1.0f / NN);
    float var = s2 * (1.0f / NN) - mean * mean;
    float sc = rsqrtf(var + EPS_BN) * __ldg(&g1[c]);
    g_stats[256 + c] = sc;
    g_stats[384 + c] = __ldg(&be1[c]) - mean * sc;
    g_stats[c] = 0.f;
    g_stats[128 + c] = 0.f;
    g_stats[512 + c] = 0.f;
}

// ---------------- launcher ----------------
extern "C" void kernel_launch(void* const* d_in, const int* in_sizes, int n_in,
                              void* d_out, int out_size) {
    const float* x  = (const float*)d_in[0];
    const int* ei   = (const int*)d_in[1];
    const float* W1 = (const float*)d_in[2];
    const float* b1 = (const float*)d_in[3];
    const float* g1 = (const float*)d_in[4];
    const float* be1= (const float*)d_in[5];
    const float* W2 = (const float*)d_in[6];
    const float* b2 = (const float*)d_in[7];
    const float* g2 = (const float*)d_in[8];
    const float* be2= (const float*)d_in[9];
    const float* W3 = (const float*)d_in[10];
    const float* b3 = (const float*)d_in[11];

    const int nE = in_sizes[1] / 2;
    const int* src = ei;
    const int* dst = ei + nE;
    const int nHalf = (nE + 1) / 2;

    // CSR build + prep (self-cleaning; no init kernel)
    k_deg<<<(nE + 255) / 256, 256>>>(dst, nE);
    k_scanprep<<<NBLK, 256>>>(x);
    k_fill<<<(nHalf + 255) / 256, 256>>>(src, dst, nE, nHalf);

    // layer 1: gather fused into gemm1 (A(xW) == (Ax)W), NC-split for occupancy
    k_gemm1<<<(NN + 63) / 64, 256>>>(W1, b1);
    k_final1<<<1, 128>>>(g1, be1);

    // layer 2 (gather fuses BN stats of h2)
    k_gemm<128, 64, 2, 2><<<(NN + 31) / 32, 256>>>(W2, nullptr, nullptr, nullptr);
    k_gather<2><<<NN * 8 / 320, 320>>>(nullptr, b2);

    // layer 3 (gemm inlines final2)
    k_gemm<64, 64, 4, 3><<<(NN + 63) / 64, 256>>>(W3, g2, be2, b2);
    k_gather<3><<<NN * 8 / 320, 320>>>((float*)d_out, b3);
}

// round 15
// speedup vs baseline: 1.1382x; 1.0602x over previous
#include <cuda_runtime.h>
#include <cuda_fp16.h>
#include <math.h>

#define NN 50000
#define NBLK 196          // ceil(NN/256)
#define EPS_BN 1e-5f
#define SLOPE 0.01f

// ---------------- scratch (static device memory; no allocs) ----------------
__device__ int   g_degi[NN];
__device__ int   g_counter;
__device__ int   g_start[NN];
__device__ int   g_end[NN];
__device__ int   g_cur[NN];
__device__ int   g_csr[800000];
__device__ float g_dinv[NN];
// fp16 message buffers: 64 ch = 8 uint4 per node (8 ch per uint4 as 4x half2)
__device__ uint4 g_u1[NN * 8];
__device__ uint4 g_u2[NN * 8];
__device__ uint4 g_u3[NN * 8];
// h1 in fp16: 128 ch = 16 uint4 per node
__device__ uint4 g_h1h[NN * 16];
__device__ float g_acc2[NN * 64];
// stats layout:
// [0:128) sum1  [128:256) sumsq1  [256:384) scale1  [384:512) shift1
// [512:576) sum2 [576:640) sumsq2
__device__ float g_stats[1024];

__device__ __forceinline__ float lrelu(float v) { return v > 0.f ? v : SLOPE * v; }

__device__ __forceinline__ unsigned pack_h2(float a, float b) {
    __half2 h = __floats2half2_rn(a, b);
    return *(unsigned*)&h;
}
__device__ __forceinline__ float2 unpack_h2(unsigned v) {
    __half2 h = *(__half2*)&v;
    return __half22float2(h);
}

// ---------------- CSR build (self-cleaning; no init kernel) ----------------
__global__ void k_deg(const int* __restrict__ dst, int nE) {
    int e = blockIdx.x * blockDim.x + threadIdx.x;
    if (e < nE) atomicAdd(&g_degi[dst[e]], 1);
}

// single-kernel CSR ranges (ticket-counter scan; region order irrelevant)
// + fused prep: dinv + u1 = fp16(x * dinv). Re-zeros g_degi for next launch.
__global__ void __launch_bounds__(256) k_scanprep(const float* __restrict__ x) {
    __shared__ int sh[256];
    __shared__ float sdinv[256];
    __shared__ int sbase;
    int tid = threadIdx.x;
    int i = blockIdx.x * 256 + tid;
    int deg = 0;
    if (i < NN) {
        deg = g_degi[i];
        g_degi[i] = 0;                       // restore zeros for next launch
    }
    sh[tid] = deg;
    __syncthreads();
    #pragma unroll
    for (int off = 1; off < 256; off <<= 1) {
        int t = (tid >= off) ? sh[tid - off] : 0;
        __syncthreads();
        sh[tid] += t;
        __syncthreads();
    }
    if (tid == 255) sbase = atomicAdd(&g_counter, sh[255]);
    float d = rsqrtf((float)(deg + 1));      // +1 self loop
    sdinv[tid] = d;
    __syncthreads();
    if (i < NN) {
        int end = sbase + sh[tid];
        g_end[i] = end;
        g_start[i] = end - deg;
        g_cur[i] = end - deg;
        g_dinv[i] = d;
    }
    // u1 staging: 8 uint4 per node (8 ch each)
    int base = blockIdx.x * 2048;            // 256 nodes * 8 uint4
    #pragma unroll
    for (int q = 0; q < 8; q++) {
        int idx = base + q * 256 + tid;      // uint4 index
        if (idx < NN * 8) {
            float dd = sdinv[(idx >> 3) - blockIdx.x * 256];
            float4 va = __ldg((const float4*)x + idx * 2);
            float4 vb = __ldg((const float4*)x + idx * 2 + 1);
            g_u1[idx] = make_uint4(pack_h2(va.x * dd, va.y * dd),
                                   pack_h2(va.z * dd, va.w * dd),
                                   pack_h2(vb.x * dd, vb.y * dd),
                                   pack_h2(vb.z * dd, vb.w * dd));
        }
    }
}

// 2 edges per thread (strided halves) for MLP; resets ticket counter.
__global__ void k_fill(const int* __restrict__ src, const int* __restrict__ dst,
                       int nE, int nHalf) {
    int e = blockIdx.x * blockDim.x + threadIdx.x;
    if (e == 0) g_counter = 0;               // restore ticket for next launch
    if (e < nHalf) {
        int d0 = __ldg(&dst[e]);
        int s0 = __ldg(&src[e]);
        int e1 = e + nHalf;
        int p0 = atomicAdd(&g_cur[d0], 1);
        if (e1 < nE) {
            int d1 = __ldg(&dst[e1]);
            int s1 = __ldg(&src[e1]);
            int p1 = atomicAdd(&g_cur[d1], 1);
            g_csr[p1] = s1;
        }
        g_csr[p0] = s0;
    }
}

// ---------------- gather (CSR, 8 lanes/node, 8 ch/lane, fp16 msgs, uint4 loads) ----
// MODE 2 accumulates BN stats of h2 = dinv*acc2 + b2 into g_stats[512..]
// MODE 3 writes final output. grid: NN*8/320 = 1250 blocks exactly.
template <int MODE>
__global__ void __launch_bounds__(320) k_gather(float* __restrict__ out,
                                                const float* __restrict__ bp) {
    __shared__ float ssum[64];
    __shared__ float ssq[64];
    int tid = threadIdx.x;
    if (MODE == 2) {
        if (tid < 64) ssum[tid] = 0.f;
        else if (tid < 128) ssq[tid - 64] = 0.f;
        __syncthreads();
    }
    int t = blockIdx.x * 320 + tid;          // uint4 slot: [0, NN*8)
    int g = t >> 3, lane = t & 7;
    const uint4* u = (MODE == 2) ? g_u2 : g_u3;

    float acc[8];
    {   // self-loop term
        uint4 r = __ldg(u + t);
        float2 p0 = unpack_h2(r.x), p1 = unpack_h2(r.y);
        float2 p2 = unpack_h2(r.z), p3 = unpack_h2(r.w);
        acc[0] = p0.x; acc[1] = p0.y; acc[2] = p1.x; acc[3] = p1.y;
        acc[4] = p2.x; acc[5] = p2.y; acc[6] = p3.x; acc[7] = p3.y;
    }
    int j = __ldg(&g_start[g]);
    int end = __ldg(&g_end[g]);
    for (; j + 3 < end; j += 4) {
        int s0 = __ldg(&g_csr[j]);
        int s1 = __ldg(&g_csr[j + 1]);
        int s2 = __ldg(&g_csr[j + 2]);
        int s3 = __ldg(&g_csr[j + 3]);
        uint4 r0 = __ldg(u + s0 * 8 + lane);
        uint4 r1 = __ldg(u + s1 * 8 + lane);
        uint4 r2 = __ldg(u + s2 * 8 + lane);
        uint4 r3 = __ldg(u + s3 * 8 + lane);
        float2 q0, q1;
        q0 = unpack_h2(r0.x); q1 = unpack_h2(r1.x);
        acc[0] += q0.x + q1.x; acc[1] += q0.y + q1.y;
        q0 = unpack_h2(r0.y); q1 = unpack_h2(r1.y);
        acc[2] += q0.x + q1.x; acc[3] += q0.y + q1.y;
        q0 = unpack_h2(r0.z); q1 = unpack_h2(r1.z);
        acc[4] += q0.x + q1.x; acc[5] += q0.y + q1.y;
        q0 = unpack_h2(r0.w); q1 = unpack_h2(r1.w);
        acc[6] += q0.x + q1.x; acc[7] += q0.y + q1.y;
        q0 = unpack_h2(r2.x); q1 = unpack_h2(r3.x);
        acc[0] += q0.x + q1.x; acc[1] += q0.y + q1.y;
        q0 = unpack_h2(r2.y); q1 = unpack_h2(r3.y);
        acc[2] += q0.x + q1.x; acc[3] += q0.y + q1.y;
        q0 = unpack_h2(r2.z); q1 = unpack_h2(r3.z);
        acc[4] += q0.x + q1.x; acc[5] += q0.y + q1.y;
        q0 = unpack_h2(r2.w); q1 = unpack_h2(r3.w);
        acc[6] += q0.x + q1.x; acc[7] += q0.y + q1.y;
    }
    for (; j < end; j++) {
        int s0 = __ldg(&g_csr[j]);
        uint4 r0 = __ldg(u + s0 * 8 + lane);
        float2 p0 = unpack_h2(r0.x), p1 = unpack_h2(r0.y);
        float2 p2 = unpack_h2(r0.z), p3 = unpack_h2(r0.w);
        acc[0] += p0.x; acc[1] += p0.y; acc[2] += p1.x; acc[3] += p1.y;
        acc[4] += p2.x; acc[5] += p2.y; acc[6] += p3.x; acc[7] += p3.y;
    }

    if (MODE == 2) {
        ((float4*)g_acc2)[t * 2]     = make_float4(acc[0], acc[1], acc[2], acc[3]);
        ((float4*)g_acc2)[t * 2 + 1] = make_float4(acc[4], acc[5], acc[6], acc[7]);
        // fused BN stats of h2 = dinv*acc + b2
        float d = g_dinv[g];
        float4 ba = __ldg((const float4*)bp + lane * 2);
        float4 bb = __ldg((const float4*)bp + lane * 2 + 1);
        float v[8], q[8];
        v[0] = fmaf(acc[0], d, ba.x); v[1] = fmaf(acc[1], d, ba.y);
        v[2] = fmaf(acc[2], d, ba.z); v[3] = fmaf(acc[3], d, ba.w);
        v[4] = fmaf(acc[4], d, bb.x); v[5] = fmaf(acc[5], d, bb.y);
        v[6] = fmaf(acc[6], d, bb.z); v[7] = fmaf(acc[7], d, bb.w);
        #pragma unroll
        for (int c = 0; c < 8; c++) q[c] = v[c] * v[c];
        #pragma unroll
        for (int c = 0; c < 8; c++) {
            v[c] += __shfl_xor_sync(0xffffffffu, v[c], 8);
            v[c] += __shfl_xor_sync(0xffffffffu, v[c], 16);
            q[c] += __shfl_xor_sync(0xffffffffu, q[c], 8);
            q[c] += __shfl_xor_sync(0xffffffffu, q[c], 16);
        }
        if ((tid & 31) < 8) {
            #pragma unroll
            for (int c = 0; c < 8; c++) {
                atomicAdd(&ssum[lane * 8 + c], v[c]);
                atomicAdd(&ssq[lane * 8 + c], q[c]);
            }
        }
        __syncthreads();
        if (tid < 64) {
            atomicAdd(&g_stats[512 + tid], ssum[tid]);
            atomicAdd(&g_stats[576 + tid], ssq[tid]);
        }
    } else {
        float d = g_dinv[g];
        float4 ba = __ldg((const float4*)bp + lane * 2);
        float4 bb = __ldg((const float4*)bp + lane * 2 + 1);
        ((float4*)out)[t * 2] = make_float4(fmaf(acc[0], d, ba.x), fmaf(acc[1], d, ba.y),
                                            fmaf(acc[2], d, ba.z), fmaf(acc[3], d, ba.w));
        ((float4*)out)[t * 2 + 1] = make_float4(fmaf(acc[4], d, bb.x), fmaf(acc[5], d, bb.y),
                                                fmaf(acc[6], d, bb.z), fmaf(acc[7], d, bb.w));
    }
}

// ---------------- layer-1 fused gather+GEMM (NC-split for occupancy) ----------------
// in = dinv * (CSR-sum of u1) (64, fp16 Is tile) -> W1 (two 64-col halves) -> +b1
// -> h1(fp16) + BN stats. smem 25KB, launch_bounds(256,4) -> 4 blocks/SM.
__global__ void __launch_bounds__(256, 4) k_gemm1(const float* __restrict__ Wg,
                                                  const float* __restrict__ bias) {
    __shared__ float Ws[64 * 64];        // 16KB: one NC-half
    __shared__ unsigned Ish[64 * 32];    // 8KB: 64 rows x 32 half2 words
    __shared__ float ssum[128];
    __shared__ float ssq[128];

    const int tid = threadIdx.x;
    const int row0 = blockIdx.x * 64;

    if (tid < 128) ssum[tid] = 0.f;
    else ssq[tid - 128] = 0.f;

    // ---- gather staging: 4 threads per row, 16 channels each (2 uint4 slots) ----
    {
        int rloc = tid >> 2;          // 0..63
        int seg = tid & 3;            // 0..3
        int gr = row0 + rloc;
        float av[16];
        #pragma unroll
        for (int c = 0; c < 16; c++) av[c] = 0.f;
        if (gr < NN) {
            const uint4* up = g_u1 + seg * 2;
            {   // self term
                uint4 ra = __ldg(up + gr * 8);
                uint4 rb = __ldg(up + gr * 8 + 1);
                float2 p;
                p = unpack_h2(ra.x); av[0] = p.x; av[1] = p.y;
                p = unpack_h2(ra.y); av[2] = p.x; av[3] = p.y;
                p = unpack_h2(ra.z); av[4] = p.x; av[5] = p.y;
                p = unpack_h2(ra.w); av[6] = p.x; av[7] = p.y;
                p = unpack_h2(rb.x); av[8] = p.x; av[9] = p.y;
                p = unpack_h2(rb.y); av[10] = p.x; av[11] = p.y;
                p = unpack_h2(rb.z); av[12] = p.x; av[13] = p.y;
                p = unpack_h2(rb.w); av[14] = p.x; av[15] = p.y;
            }
            int j = __ldg(&g_start[gr]);
            int end = __ldg(&g_end[gr]);
            for (; j + 1 < end; j += 2) {
                int s0 = __ldg(&g_csr[j]);
                int s1 = __ldg(&g_csr[j + 1]);
                uint4 ra = __ldg(up + s0 * 8);
                uint4 rb = __ldg(up + s0 * 8 + 1);
                uint4 rc = __ldg(up + s1 * 8);
                uint4 rd = __ldg(up + s1 * 8 + 1);
                float2 p, q;
                p = unpack_h2(ra.x); q = unpack_h2(rc.x); av[0] += p.x + q.x; av[1] += p.y + q.y;
                p = unpack_h2(ra.y); q = unpack_h2(rc.y); av[2] += p.x + q.x; av[3] += p.y + q.y;
                p = unpack_h2(ra.z); q = unpack_h2(rc.z); av[4] += p.x + q.x; av[5] += p.y + q.y;
                p = unpack_h2(ra.w); q = unpack_h2(rc.w); av[6] += p.x + q.x; av[7] += p.y + q.y;
                p = unpack_h2(rb.x); q = unpack_h2(rd.x); av[8] += p.x + q.x; av[9] += p.y + q.y;
                p = unpack_h2(rb.y); q = unpack_h2(rd.y); av[10] += p.x + q.x; av[11] += p.y + q.y;
                p = unpack_h2(rb.z); q = unpack_h2(rd.z); av[12] += p.x + q.x; av[13] += p.y + q.y;
                p = unpack_h2(rb.w); q = unpack_h2(rd.w); av[14] += p.x + q.x; av[15] += p.y + q.y;
            }
            if (j < end) {
                int s0 = __ldg(&g_csr[j]);
                uint4 ra = __ldg(up + s0 * 8);
                uint4 rb = __ldg(up + s0 * 8 + 1);
                float2 p;
                p = unpack_h2(ra.x); av[0] += p.x; av[1] += p.y;
                p = unpack_h2(ra.y); av[2] += p.x; av[3] += p.y;
                p = unpack_h2(ra.z); av[4] += p.x; av[5] += p.y;
                p = unpack_h2(ra.w); av[6] += p.x; av[7] += p.y;
                p = unpack_h2(rb.x); av[8] += p.x; av[9] += p.y;
                p = unpack_h2(rb.y); av[10] += p.x; av[11] += p.y;
                p = unpack_h2(rb.z); av[12] += p.x; av[13] += p.y;
                p = unpack_h2(rb.w); av[14] += p.x; av[15] += p.y;
            }
            float d = __ldg((const float*)&g_dinv[gr]);
            #pragma unroll
            for (int c = 0; c < 16; c++) av[c] *= d;
        }
        uint4* dst4 = (uint4*)(Ish + rloc * 32 + seg * 8);
        dst4[0] = make_uint4(pack_h2(av[0], av[1]), pack_h2(av[2], av[3]),
                             pack_h2(av[4], av[5]), pack_h2(av[6], av[7]));
        dst4[1] = make_uint4(pack_h2(av[8], av[9]), pack_h2(av[10], av[11]),
                             pack_h2(av[12], av[13]), pack_h2(av[14], av[15]));
    }

    const int ct = tid & 15, rt = tid >> 4;
    const unsigned* isbase = Ish + (rt * 4) * 32;
    const float4* Wg4 = (const float4*)Wg;    // 64 rows x 32 float4 (NC=128)
    float4* Ws4 = (float4*)Ws;

    #pragma unroll
    for (int h = 0; h < 2; h++) {
        if (h) __syncthreads();               // all reads of previous Ws done
        // stage W half: 64 x 64 floats = 1024 float4
        #pragma unroll
        for (int i = tid; i < 1024; i += 256) {
            int k = i >> 4, c4 = i & 15;
            Ws4[i] = __ldg(Wg4 + k * 32 + h * 16 + c4);
        }
        __syncthreads();

        float acc[4][4];
        #pragma unroll
        for (int j = 0; j < 4; j++)
            #pragma unroll
            for (int c = 0; c < 4; c++) acc[j][c] = 0.f;

        #pragma unroll 4
        for (int k4 = 0; k4 < 16; ++k4) {
            float a[4][4];
            #pragma unroll
            for (int j = 0; j < 4; j++) {
                uint2 t2 = *(const uint2*)(isbase + j * 32 + k4 * 2);
                float2 lo = unpack_h2(t2.x), hi = unpack_h2(t2.y);
                a[j][0] = lo.x; a[j][1] = lo.y; a[j][2] = hi.x; a[j][3] = hi.y;
            }
            #pragma unroll
            for (int kk = 0; kk < 4; kk++) {
                float4 w4 = *(const float4*)(Ws + (k4 * 4 + kk) * 64 + ct * 4);
                #pragma unroll
                for (int j = 0; j < 4; j++) {
                    acc[j][0] = fmaf(a[j][kk], w4.x, acc[j][0]);
                    acc[j][1] = fmaf(a[j][kk], w4.y, acc[j][1]);
                    acc[j][2] = fmaf(a[j][kk], w4.z, acc[j][2]);
                    acc[j][3] = fmaf(a[j][kk], w4.w, acc[j][3]);
                }
            }
        }

        // epilogue for this half: bias, fp16 h1 write, local stats
        float bl[4];
        #pragma unroll
        for (int c = 0; c < 4; c++) bl[c] = __ldg(&bias[h * 64 + ct * 4 + c]);
        #pragma unroll
        for (int j = 0; j < 4; j++) {
            int gr = row0 + rt * 4 + j;
            if (gr < NN) {
                #pragma unroll
                for (int c = 0; c < 4; c++) acc[j][c] += bl[c];
                ((uint2*)g_h1h)[gr * 32 + h * 16 + ct] =
                    make_uint2(pack_h2(acc[j][0], acc[j][1]),
                               pack_h2(acc[j][2], acc[j][3]));
            } else {
                #pragma unroll
                for (int c = 0; c < 4; c++) acc[j][c] = 0.f;
            }
        }
        #pragma unroll
        for (int c = 0; c < 4; c++) {
            float sv = 0.f, sq = 0.f;
            #pragma unroll
            for (int j = 0; j < 4; j++) { sv += acc[j][c]; sq += acc[j][c] * acc[j][c]; }
            atomicAdd(&ssum[h * 64 + ct * 4 + c], sv);
            atomicAdd(&ssq[h * 64 + ct * 4 + c], sq);
        }
    }
    __syncthreads();
    if (tid < 128) {
        atomicAdd(&g_stats[tid], ssum[tid]);
        atomicAdd(&g_stats[128 + tid], ssq[tid]);
    }
}

// ---------------- dense GEMM (modes 2/3, occupancy-split, fp16 Is tile) --------
// MODE 2: K=128: in = leaky(fp16(h1)*scale1+shift1) -> W2 (two K-halves) -> *dinv -> u2 fp16
// MODE 3: K=64:  in = leaky((dinv*acc2)*sc2+sh2) -> W3 -> *dinv -> u3 fp16 (inline final2)
// R=64 rows/block, 256 threads, acc[4][4], launch_bounds(256,4).
template <int K, int MODE>
__global__ void __launch_bounds__(256, 4) k_gemmd(const float* __restrict__ Wg,
                                                  const float* __restrict__ p0,
                                                  const float* __restrict__ p1,
                                                  const float* __restrict__ p2) {
    constexpr int KW = K / 2;                // half2 words per row
    __shared__ float Ws[64 * 64];            // 16KB: one K-half of W
    __shared__ unsigned Ish[64 * KW];        // MODE2: 16KB, MODE3: 8KB
    __shared__ float s_sc[K];
    __shared__ float s_sh[K];

    const int tid = threadIdx.x;
    const int row0 = blockIdx.x * 64;

    if (MODE == 3) {
        if (tid < 64) {
            float mean = g_stats[512 + tid] * (1.0f / NN);
            float var = g_stats[576 + tid] * (1.0f / NN) - mean * mean;
            float sc = rsqrtf(var + EPS_BN) * __ldg(&p0[tid]);
            s_sc[tid] = sc;
            s_sh[tid] = __ldg(&p1[tid]) + (__ldg(&p2[tid]) - mean) * sc;
        }
    } else {
        if (tid < K) {
            s_sc[tid] = g_stats[256 + tid];
            s_sh[tid] = g_stats[384 + tid];
        }
    }
    __syncthreads();

    // ---- stage input tile (fp16) with fused BN+leaky transform ----
    {
        #pragma unroll
        for (int i = tid; i < 64 * K / 4; i += 256) {
            int r = i / (K / 4), kq = i % (K / 4);   // kq: 4-channel group
            int gr = row0 + r;
            float v0 = 0.f, v1 = 0.f, v2 = 0.f, v3 = 0.f;
            if (gr < NN) {
                float4 sc = *(const float4*)(s_sc + kq * 4);
                float4 sh = *(const float4*)(s_sh + kq * 4);
                if (MODE == 2) {
                    uint2 hv = __ldg((const uint2*)g_h1h + gr * 32 + kq);
                    float2 ha = unpack_h2(hv.x), hb = unpack_h2(hv.y);
                    v0 = lrelu(fmaf(ha.x, sc.x, sh.x));
                    v1 = lrelu(fmaf(ha.y, sc.y, sh.y));
                    v2 = lrelu(fmaf(hb.x, sc.z, sh.z));
                    v3 = lrelu(fmaf(hb.y, sc.w, sh.w));
                } else {
                    float4 a = __ldg((const float4*)g_acc2 + gr * 16 + kq);
                    float d = __ldg((const float*)&g_dinv[gr]);
                    v0 = lrelu(fmaf(a.x * d, sc.x, sh.x));
                    v1 = lrelu(fmaf(a.y * d, sc.y, sh.y));
                    v2 = lrelu(fmaf(a.z * d, sc.z, sh.z));
                    v3 = lrelu(fmaf(a.w * d, sc.w, sh.w));
                }
            }
            *(uint2*)(Ish + r * KW + kq * 2) = make_uint2(pack_h2(v0, v1), pack_h2(v2, v3));
        }
    }

    const int ct = tid & 15, rt = tid >> 4;
    const unsigned* isbase = Ish + (rt * 4) * KW;
    const float4* Wg4 = (const float4*)Wg;    // K rows x 16 float4 (NC=64)
    float4* Ws4 = (float4*)Ws;

    float acc[4][4];
    #pragma unroll
    for (int j = 0; j < 4; j++)
        #pragma unroll
        for (int c = 0; c < 4; c++) acc[j][c] = 0.f;

    constexpr int NH = K / 64;                // K-halves
    #pragma unroll
    for (int h = 0; h < NH; h++) {
        __syncthreads();                      // Is staged / previous Ws reads done
        // stage W K-half: rows h*64..h*64+63, all 64 cols = 1024 float4
        #pragma unroll
        for (int i = tid; i < 1024; i += 256) {
            Ws4[i] = __ldg(Wg4 + h * 1024 + i);
        }
        __syncthreads();

        #pragma unroll 4
        for (int k4 = 0; k4 < 16; ++k4) {
            float a[4][4];
            #pragma unroll
            for (int j = 0; j < 4; j++) {
                uint2 t2 = *(const uint2*)(isbase + j * KW + (h * 16 + k4) * 2);
                float2 lo = unpack_h2(t2.x), hi = unpack_h2(t2.y);
                a[j][0] = lo.x; a[j][1] = lo.y; a[j][2] = hi.x; a[j][3] = hi.y;
            }
            #pragma unroll
            for (int kk = 0; kk < 4; kk++) {
                float4 w4 = *(const float4*)(Ws + (k4 * 4 + kk) * 64 + ct * 4);
                #pragma unroll
                for (int j = 0; j < 4; j++) {
                    acc[j][0] = fmaf(a[j][kk], w4.x, acc[j][0]);
                    acc[j][1] = fmaf(a[j][kk], w4.y, acc[j][1]);
                    acc[j][2] = fmaf(a[j][kk], w4.z, acc[j][2]);
                    acc[j][3] = fmaf(a[j][kk], w4.w, acc[j][3]);
                }
            }
        }
    }

    uint2* o0 = (MODE == 2) ? (uint2*)g_u2 : (uint2*)g_u3;
    #pragma unroll
    for (int j = 0; j < 4; j++) {
        int gr = row0 + rt * 4 + j;
        if (gr >= NN) continue;
        float d = __ldg((const float*)&g_dinv[gr]);
        o0[gr * 16 + ct] = make_uint2(pack_h2(acc[j][0] * d, acc[j][1] * d),
                                      pack_h2(acc[j][2] * d, acc[j][3] * d));
    }
}

// consumes stats[0..255] -> scale1/shift1; zeros [0..255] (next launch's gemm1)
// and [512..639] (this launch's gather2 accumulation).
__global__ void k_final1(const float* __restrict__ g1, const float* __restrict__ be1) {
    int c = threadIdx.x;  // 128
    float s1 = g_stats[c];
    float s2 = g_stats[128 + c];
    float mean = s1 * (1.0f / NN);
    float var = s2 * (1.0f / NN) - mean * mean;
    float sc = rsqrtf(var + EPS_BN) * __ldg(&g1[c]);
    g_stats[256 + c] = sc;
    g_stats[384 + c] = __ldg(&be1[c]) - mean * sc;
    g_stats[c] = 0.f;
    g_stats[128 + c] = 0.f;
    g_stats[512 + c] = 0.f;
}

// ---------------- launcher ----------------
extern "C" void kernel_launch(void* const* d_in, const int* in_sizes, int n_in,
                              void* d_out, int out_size) {
    const float* x  = (const float*)d_in[0];
    const int* ei   = (const int*)d_in[1];
    const float* W1 = (const float*)d_in[2];
    const float* b1 = (const float*)d_in[3];
    const float* g1 = (const float*)d_in[4];
    const float* be1= (const float*)d_in[5];
    const float* W2 = (const float*)d_in[6];
    const float* b2 = (const float*)d_in[7];
    const float* g2 = (const float*)d_in[8];
    const float* be2= (const float*)d_in[9];
    const float* W3 = (const float*)d_in[10];
    const float* b3 = (const float*)d_in[11];

    const int nE = in_sizes[1] / 2;
    const int* src = ei;
    const int* dst = ei + nE;
    const int nHalf = (nE + 1) / 2;

    // CSR build + prep (self-cleaning; no init kernel)
    k_deg<<<(nE + 255) / 256, 256>>>(dst, nE);
    k_scanprep<<<NBLK, 256>>>(x);
    k_fill<<<(nHalf + 255) / 256, 256>>>(src, dst, nE, nHalf);

    // layer 1: gather fused into gemm1 (A(xW) == (Ax)W), NC-split for occupancy
    k_gemm1<<<(NN + 63) / 64, 256>>>(W1, b1);
    k_final1<<<1, 128>>>(g1, be1);

    // layer 2 (gather fuses BN stats of h2)
    k_gemmd<128, 2><<<(NN + 63) / 64, 256>>>(W2, nullptr, nullptr, nullptr);
    k_gather<2><<<NN * 8 / 320, 320>>>(nullptr, b2);

    // layer 3 (gemm inlines final2)
    k_gemmd<64, 3><<<(NN + 63) / 64, 256>>>(W3, g2, be2, b2);
    k_gather<3><<<NN * 8 / 320, 320>>>((float*)d_out, b3);
}